// round 15
// baseline (speedup 1.0000x reference)
#include <cuda_runtime.h>
#include <cuda_bf16.h>
#include <cstdint>

// Problem shape (fixed by dataset): B=32, N=1024, D=512, k=N/2=512.
#define NB 32
#define NN 1024
#define ND 512
#define KSEL 512
#define EPSF 1e-8f

__device__ float g_r[NB * NN];              // per-row inverse norms
__device__ float g_Spart[NB * 8 * ND];      // per-block partial unit-sums
__device__ float g_scores[NB * NN];         // per-row scores
__device__ int   g_sel[NB * KSEL];          // selected row indices
__device__ float g_part2[NB * 32 * ND];     // gather partials (32 per batch)

// ---------------------------------------------------------------------------
// K1: per-row inverse norm + per-block partial S = sum_n r_n * x_n
// grid = B*8, 512 threads (16 warps); block owns 128 rows, warp owns 8.
// ---------------------------------------------------------------------------
__global__ __launch_bounds__(512) void k1_norms_ssum(const float* __restrict__ x) {
    __shared__ float sh[16 * ND];  // 32 KB per-warp partial S
    const int blk = blockIdx.x;
    const int b = blk >> 3, p = blk & 7;
    const int tid = threadIdx.x;
    const int w = tid >> 5, lane = tid & 31;

    const float4* __restrict__ X =
        reinterpret_cast<const float4*>(x) + (size_t)b * NN * (ND / 4);

    float4 a0 = make_float4(0.f, 0.f, 0.f, 0.f);
    float4 a1 = a0, a2 = a0, a3 = a0;

    const int row0 = p * 128 + w * 8;
#pragma unroll
    for (int rr = 0; rr < 8; rr++) {
        const int row = row0 + rr;
        const float4* xr = X + (size_t)row * (ND / 4);
        float4 v0 = xr[lane];
        float4 v1 = xr[lane + 32];
        float4 v2 = xr[lane + 64];
        float4 v3 = xr[lane + 96];
        float ss = v0.x * v0.x + v0.y * v0.y + v0.z * v0.z + v0.w * v0.w
                 + v1.x * v1.x + v1.y * v1.y + v1.z * v1.z + v1.w * v1.w
                 + v2.x * v2.x + v2.y * v2.y + v2.z * v2.z + v2.w * v2.w
                 + v3.x * v3.x + v3.y * v3.y + v3.z * v3.z + v3.w * v3.w;
#pragma unroll
        for (int o = 16; o > 0; o >>= 1) ss += __shfl_xor_sync(0xffffffffu, ss, o);
        const float r = 1.0f / fmaxf(sqrtf(ss), EPSF);
        if (lane == 0) g_r[b * NN + row] = r;
        a0.x += r * v0.x; a0.y += r * v0.y; a0.z += r * v0.z; a0.w += r * v0.w;
        a1.x += r * v1.x; a1.y += r * v1.y; a1.z += r * v1.z; a1.w += r * v1.w;
        a2.x += r * v2.x; a2.y += r * v2.y; a2.z += r * v2.z; a2.w += r * v2.w;
        a3.x += r * v3.x; a3.y += r * v3.y; a3.z += r * v3.z; a3.w += r * v3.w;
    }
    float4* shv = reinterpret_cast<float4*>(sh);
    shv[w * 128 + lane]      = a0;
    shv[w * 128 + lane + 32] = a1;
    shv[w * 128 + lane + 64] = a2;
    shv[w * 128 + lane + 96] = a3;
    __syncthreads();

    float s = 0.f;
#pragma unroll
    for (int ww = 0; ww < 16; ww++) s += sh[ww * ND + tid];
    g_Spart[(size_t)blk * ND + tid] = s;
}

// ---------------------------------------------------------------------------
// K2: combine partials into S (in-block, redundantly) then
//     score_n = r_n * dot(x_n, S_b). grid = B*8, 512 threads.
// ---------------------------------------------------------------------------
__global__ __launch_bounds__(512) void k2_scores(const float* __restrict__ x) {
    __shared__ float S[ND];
    const int blk = blockIdx.x;
    const int b = blk >> 3, p = blk & 7;
    const int tid = threadIdx.x;
    const int w = tid >> 5, lane = tid & 31;

    float sacc = 0.f;
#pragma unroll
    for (int q = 0; q < 8; q++) sacc += g_Spart[((size_t)b * 8 + q) * ND + tid];
    S[tid] = sacc;
    __syncthreads();

    const float4* Sv = reinterpret_cast<const float4*>(S);
    const float4 s0 = Sv[lane];
    const float4 s1 = Sv[lane + 32];
    const float4 s2 = Sv[lane + 64];
    const float4 s3 = Sv[lane + 96];

    const float4* __restrict__ X =
        reinterpret_cast<const float4*>(x) + (size_t)b * NN * (ND / 4);

    const int row0 = p * 128 + w * 8;
#pragma unroll
    for (int rr = 0; rr < 8; rr++) {
        const int row = row0 + rr;
        const float4* xr = X + (size_t)row * (ND / 4);
        float4 v0 = xr[lane];
        float4 v1 = xr[lane + 32];
        float4 v2 = xr[lane + 64];
        float4 v3 = xr[lane + 96];
        float dt = v0.x * s0.x + v0.y * s0.y + v0.z * s0.z + v0.w * s0.w
                 + v1.x * s1.x + v1.y * s1.y + v1.z * s1.z + v1.w * s1.w
                 + v2.x * s2.x + v2.y * s2.y + v2.z * s2.z + v2.w * s2.w
                 + v3.x * s3.x + v3.y * s3.y + v3.z * s3.z + v3.w * s3.w;
#pragma unroll
        for (int o = 16; o > 0; o >>= 1) dt += __shfl_xor_sync(0xffffffffu, dt, o);
        if (lane == 0) g_scores[b * NN + row] = g_r[b * NN + row] * dt;
    }
}

// ---------------------------------------------------------------------------
// K3: per-batch top-512 set via MSD radix-select on distinct 64-bit keys.
// grid = B, 1024 threads.
// ---------------------------------------------------------------------------
__global__ __launch_bounds__(1024) void k3_select(void) {
    __shared__ int hist[256];
    __shared__ int sh_digit, sh_k;
    __shared__ unsigned long long sh_T;
    __shared__ int warp_off[32];

    const int b = blockIdx.x, tid = threadIdx.x;
    const int lane = tid & 31, wid = tid >> 5;

    unsigned u = __float_as_uint(g_scores[b * NN + tid]);
    u ^= (u >> 31) ? 0xFFFFFFFFu : 0x80000000u;
    const unsigned long long key =
        ((unsigned long long)u << 32) | (unsigned)(NN - 1 - tid);

    bool active = true;
    int k = KSEL;

    for (int shift = 56; shift >= 0; shift -= 8) {
        if (tid < 256) hist[tid] = 0;
        __syncthreads();
        const int d = (int)((key >> shift) & 255);
        if (active) atomicAdd(&hist[d], 1);
        __syncthreads();

        if (tid < 32) {
            const int base = 255 - tid * 8;
            int c[8], t = 0;
#pragma unroll
            for (int j = 0; j < 8; j++) { c[j] = hist[base - j]; t += c[j]; }
            int inc = t;
#pragma unroll
            for (int o = 1; o < 32; o <<= 1) {
                int v = __shfl_up_sync(0xffffffffu, inc, o);
                if (tid >= o) inc += v;
            }
            const int excl = inc - t;
            if (excl < k && excl + t >= k) {
                int s = excl, found = -1, newk = 0;
#pragma unroll
                for (int j = 0; j < 8; j++) {
                    if (found < 0 && s + c[j] >= k) { found = base - j; newk = k - s; }
                    s += c[j];
                }
                sh_digit = found; sh_k = newk;
            }
        }
        __syncthreads();
        const int seld = sh_digit;
        k = sh_k;
        active = active && (d == seld);
        const bool done = (hist[seld] == 1);
        if (active && done) sh_T = key;
        __syncthreads();
        if (done) break;
    }
    const unsigned long long T = sh_T;

    const bool sel = (key >= T);
    const unsigned bal = __ballot_sync(0xffffffffu, sel);
    const int rank = __popc(bal & ((1u << lane) - 1));
    if (lane == 0) warp_off[wid] = __popc(bal);
    __syncthreads();
    if (tid < 32) {
        int v = warp_off[tid];
        int inc = v;
#pragma unroll
        for (int o = 1; o < 32; o <<= 1) {
            int t2 = __shfl_up_sync(0xffffffffu, inc, o);
            if (tid >= o) inc += t2;
        }
        warp_off[tid] = inc - v;
    }
    __syncthreads();
    if (sel) g_sel[b * KSEL + warp_off[wid] + rank] = tid;
}

// ---------------------------------------------------------------------------
// K4: vectorized gather partials. grid = B*8, 512 threads.
// Block (b,p) sums 64 selected rows. Thread layout: rl = tid>>7 (0..3),
// dg = tid&127 (float4 group). Each thread: 16 independent LDG.128.
// Writes 4 partials per block → g_part2[(blk*4+rl)*ND ..].
// ---------------------------------------------------------------------------
__global__ __launch_bounds__(512) void k4_gather(const float* __restrict__ x) {
    __shared__ int sidx[64];
    const int blk = blockIdx.x;
    const int b = blk >> 3, p = blk & 7;
    const int tid = threadIdx.x;
    const int rl = tid >> 7, dg = tid & 127;

    if (tid < 64) sidx[tid] = g_sel[b * KSEL + p * 64 + tid];
    __syncthreads();

    const float4* __restrict__ Xv =
        reinterpret_cast<const float4*>(x) + (size_t)b * NN * 128;

    float4 acc = make_float4(0.f, 0.f, 0.f, 0.f);
#pragma unroll
    for (int t = 0; t < 16; t++) {
        const int row = sidx[rl + 4 * t];
        const float4 v = Xv[(size_t)row * 128 + dg];
        acc.x += v.x; acc.y += v.y; acc.z += v.z; acc.w += v.w;
    }
    float4* __restrict__ P = reinterpret_cast<float4*>(g_part2);
    P[((size_t)blk * 4 + rl) * 128 + dg] = acc;
}

// K5: final combine + mean over 32 partials per batch. grid = B, 512 threads.
__global__ __launch_bounds__(512) void k5_final(float* __restrict__ out) {
    const int b = blockIdx.x, d = threadIdx.x;
    float s = 0.f;
#pragma unroll
    for (int q = 0; q < 32; q++) s += g_part2[((size_t)b * 32 + q) * ND + d];
    out[b * ND + d] = s * (1.0f / (float)KSEL);
}

extern "C" void kernel_launch(void* const* d_in, const int* in_sizes, int n_in,
                              void* d_out, int out_size) {
    const float* x = (const float*)d_in[0];
    float* out = (float*)d_out;
    const int B = in_sizes[0] / (NN * ND);   // 32

    k1_norms_ssum<<<B * 8, 512>>>(x);
    k2_scores<<<B * 8, 512>>>(x);
    k3_select<<<B, 1024>>>();
    k4_gather<<<B * 8, 512>>>(x);
    k5_final<<<B, 512>>>(out);
}

// round 16
// speedup vs baseline: 1.0804x; 1.0804x over previous
#include <cuda_runtime.h>
#include <cuda_bf16.h>
#include <cstdint>

// Problem shape (fixed by dataset): B=32, N=1024, D=512, k=N/2=512.
#define NB 32
#define NN 1024
#define ND 512
#define KSEL 512
#define EPSF 1e-8f

__device__ float g_r[NB * NN];              // per-row inverse norms
__device__ float g_Spart[NB * 8 * ND];      // per-block partial unit-sums
__device__ float g_scores[NB * NN];         // per-row scores
__device__ int   g_sel[NB * KSEL];          // selected row indices
__device__ float g_part2[NB * 32 * ND];     // gather partials (32 per batch)

// ---------------------------------------------------------------------------
// K1: per-row inverse norm + per-block partial S = sum_n r_n * x_n
// grid = B*8, 512 threads (16 warps); block owns 128 rows, warp owns 8.
// ---------------------------------------------------------------------------
__global__ __launch_bounds__(512) void k1_norms_ssum(const float* __restrict__ x) {
    __shared__ float sh[16 * ND];  // 32 KB per-warp partial S
    const int blk = blockIdx.x;
    const int b = blk >> 3, p = blk & 7;
    const int tid = threadIdx.x;
    const int w = tid >> 5, lane = tid & 31;

    const float4* __restrict__ X =
        reinterpret_cast<const float4*>(x) + (size_t)b * NN * (ND / 4);

    float4 a0 = make_float4(0.f, 0.f, 0.f, 0.f);
    float4 a1 = a0, a2 = a0, a3 = a0;

    const int row0 = p * 128 + w * 8;
#pragma unroll
    for (int rr = 0; rr < 8; rr++) {
        const int row = row0 + rr;
        const float4* xr = X + (size_t)row * (ND / 4);
        float4 v0 = xr[lane];
        float4 v1 = xr[lane + 32];
        float4 v2 = xr[lane + 64];
        float4 v3 = xr[lane + 96];
        float ss = v0.x * v0.x + v0.y * v0.y + v0.z * v0.z + v0.w * v0.w
                 + v1.x * v1.x + v1.y * v1.y + v1.z * v1.z + v1.w * v1.w
                 + v2.x * v2.x + v2.y * v2.y + v2.z * v2.z + v2.w * v2.w
                 + v3.x * v3.x + v3.y * v3.y + v3.z * v3.z + v3.w * v3.w;
#pragma unroll
        for (int o = 16; o > 0; o >>= 1) ss += __shfl_xor_sync(0xffffffffu, ss, o);
        const float r = 1.0f / fmaxf(sqrtf(ss), EPSF);
        if (lane == 0) g_r[b * NN + row] = r;
        a0.x += r * v0.x; a0.y += r * v0.y; a0.z += r * v0.z; a0.w += r * v0.w;
        a1.x += r * v1.x; a1.y += r * v1.y; a1.z += r * v1.z; a1.w += r * v1.w;
        a2.x += r * v2.x; a2.y += r * v2.y; a2.z += r * v2.z; a2.w += r * v2.w;
        a3.x += r * v3.x; a3.y += r * v3.y; a3.z += r * v3.z; a3.w += r * v3.w;
    }
    float4* shv = reinterpret_cast<float4*>(sh);
    shv[w * 128 + lane]      = a0;
    shv[w * 128 + lane + 32] = a1;
    shv[w * 128 + lane + 64] = a2;
    shv[w * 128 + lane + 96] = a3;
    __syncthreads();

    float s = 0.f;
#pragma unroll
    for (int ww = 0; ww < 16; ww++) s += sh[ww * ND + tid];
    g_Spart[(size_t)blk * ND + tid] = s;
}

// ---------------------------------------------------------------------------
// K2: combine partials into S (in-block, redundantly) then
//     score_n = r_n * dot(x_n, S_b). grid = B*8, 512 threads.
// ---------------------------------------------------------------------------
__global__ __launch_bounds__(512) void k2_scores(const float* __restrict__ x) {
    __shared__ float S[ND];
    const int blk = blockIdx.x;
    const int b = blk >> 3, p = blk & 7;
    const int tid = threadIdx.x;
    const int w = tid >> 5, lane = tid & 31;

    float sacc = 0.f;
#pragma unroll
    for (int q = 0; q < 8; q++) sacc += g_Spart[((size_t)b * 8 + q) * ND + tid];
    S[tid] = sacc;
    __syncthreads();

    const float4* Sv = reinterpret_cast<const float4*>(S);
    const float4 s0 = Sv[lane];
    const float4 s1 = Sv[lane + 32];
    const float4 s2 = Sv[lane + 64];
    const float4 s3 = Sv[lane + 96];

    const float4* __restrict__ X =
        reinterpret_cast<const float4*>(x) + (size_t)b * NN * (ND / 4);

    const int row0 = p * 128 + w * 8;
#pragma unroll
    for (int rr = 0; rr < 8; rr++) {
        const int row = row0 + rr;
        const float4* xr = X + (size_t)row * (ND / 4);
        float4 v0 = xr[lane];
        float4 v1 = xr[lane + 32];
        float4 v2 = xr[lane + 64];
        float4 v3 = xr[lane + 96];
        float dt = v0.x * s0.x + v0.y * s0.y + v0.z * s0.z + v0.w * s0.w
                 + v1.x * s1.x + v1.y * s1.y + v1.z * s1.z + v1.w * s1.w
                 + v2.x * s2.x + v2.y * s2.y + v2.z * s2.z + v2.w * s2.w
                 + v3.x * s3.x + v3.y * s3.y + v3.z * s3.z + v3.w * s3.w;
#pragma unroll
        for (int o = 16; o > 0; o >>= 1) dt += __shfl_xor_sync(0xffffffffu, dt, o);
        if (lane == 0) g_scores[b * NN + row] = g_r[b * NN + row] * dt;
    }
}

// ---------------------------------------------------------------------------
// K3: per-batch top-512 set via MSD radix-select on distinct 64-bit keys.
// grid = B, 1024 threads.
// ---------------------------------------------------------------------------
__global__ __launch_bounds__(1024) void k3_select(void) {
    __shared__ int hist[256];
    __shared__ int sh_digit, sh_k;
    __shared__ unsigned long long sh_T;
    __shared__ int warp_off[32];

    const int b = blockIdx.x, tid = threadIdx.x;
    const int lane = tid & 31, wid = tid >> 5;

    unsigned u = __float_as_uint(g_scores[b * NN + tid]);
    u ^= (u >> 31) ? 0xFFFFFFFFu : 0x80000000u;
    const unsigned long long key =
        ((unsigned long long)u << 32) | (unsigned)(NN - 1 - tid);

    bool active = true;
    int k = KSEL;

    for (int shift = 56; shift >= 0; shift -= 8) {
        if (tid < 256) hist[tid] = 0;
        __syncthreads();
        const int d = (int)((key >> shift) & 255);
        if (active) atomicAdd(&hist[d], 1);
        __syncthreads();

        if (tid < 32) {
            const int base = 255 - tid * 8;
            int c[8], t = 0;
#pragma unroll
            for (int j = 0; j < 8; j++) { c[j] = hist[base - j]; t += c[j]; }
            int inc = t;
#pragma unroll
            for (int o = 1; o < 32; o <<= 1) {
                int v = __shfl_up_sync(0xffffffffu, inc, o);
                if (tid >= o) inc += v;
            }
            const int excl = inc - t;
            if (excl < k && excl + t >= k) {
                int s = excl, found = -1, newk = 0;
#pragma unroll
                for (int j = 0; j < 8; j++) {
                    if (found < 0 && s + c[j] >= k) { found = base - j; newk = k - s; }
                    s += c[j];
                }
                sh_digit = found; sh_k = newk;
            }
        }
        __syncthreads();
        const int seld = sh_digit;
        k = sh_k;
        active = active && (d == seld);
        const bool done = (hist[seld] == 1);
        if (active && done) sh_T = key;
        __syncthreads();
        if (done) break;
    }
    const unsigned long long T = sh_T;

    const bool sel = (key >= T);
    const unsigned bal = __ballot_sync(0xffffffffu, sel);
    const int rank = __popc(bal & ((1u << lane) - 1));
    if (lane == 0) warp_off[wid] = __popc(bal);
    __syncthreads();
    if (tid < 32) {
        int v = warp_off[tid];
        int inc = v;
#pragma unroll
        for (int o = 1; o < 32; o <<= 1) {
            int t2 = __shfl_up_sync(0xffffffffu, inc, o);
            if (tid >= o) inc += t2;
        }
        warp_off[tid] = inc - v;
    }
    __syncthreads();
    if (sel) g_sel[b * KSEL + warp_off[wid] + rank] = tid;
}

// ---------------------------------------------------------------------------
// K4: vectorized gather partials. grid = B*8, 512 threads.
// Block (b,p) sums 64 selected rows. Thread layout: rl = tid>>7 (0..3),
// dg = tid&127 (float4 group). Each thread: 16 independent LDG.128.
// Writes 4 partials per block → g_part2[(blk*4+rl)*ND ..].
// ---------------------------------------------------------------------------
__global__ __launch_bounds__(512) void k4_gather(const float* __restrict__ x) {
    __shared__ int sidx[64];
    const int blk = blockIdx.x;
    const int b = blk >> 3, p = blk & 7;
    const int tid = threadIdx.x;
    const int rl = tid >> 7, dg = tid & 127;

    if (tid < 64) sidx[tid] = g_sel[b * KSEL + p * 64 + tid];
    __syncthreads();

    const float4* __restrict__ Xv =
        reinterpret_cast<const float4*>(x) + (size_t)b * NN * 128;

    float4 acc = make_float4(0.f, 0.f, 0.f, 0.f);
#pragma unroll
    for (int t = 0; t < 16; t++) {
        const int row = sidx[rl + 4 * t];
        const float4 v = Xv[(size_t)row * 128 + dg];
        acc.x += v.x; acc.y += v.y; acc.z += v.z; acc.w += v.w;
    }
    float4* __restrict__ P = reinterpret_cast<float4*>(g_part2);
    P[((size_t)blk * 4 + rl) * 128 + dg] = acc;
}

// K5: final combine + mean over 32 partials per batch. grid = B, 512 threads.
__global__ __launch_bounds__(512) void k5_final(float* __restrict__ out) {
    const int b = blockIdx.x, d = threadIdx.x;
    float s = 0.f;
#pragma unroll
    for (int q = 0; q < 32; q++) s += g_part2[((size_t)b * 32 + q) * ND + d];
    out[b * ND + d] = s * (1.0f / (float)KSEL);
}

extern "C" void kernel_launch(void* const* d_in, const int* in_sizes, int n_in,
                              void* d_out, int out_size) {
    const float* x = (const float*)d_in[0];
    float* out = (float*)d_out;
    const int B = in_sizes[0] / (NN * ND);   // 32

    k1_norms_ssum<<<B * 8, 512>>>(x);
    k2_scores<<<B * 8, 512>>>(x);
    k3_select<<<B, 1024>>>();
    k4_gather<<<B * 8, 512>>>(x);
    k5_final<<<B, 512>>>(out);
}